// round 1
// baseline (speedup 1.0000x reference)
#include <cuda_runtime.h>
#include <math.h>
#include <float.h>

#define BB 32
#define HH 56
#define WW 56
#define CC 256
#define HW (HH*WW)

// ---------------- scratch (device globals; no allocation allowed) ----------------
__device__ float g_pool1[BB*HH*CC*2];   // [b][h][c][{max,mean over W}]
__device__ float g_pool2[BB*CC*WW*2];   // [b][c][w][{max,mean over H}]
__device__ float g_pool3[BB*HH*WW*2];   // [b][h][w][{max,mean over C}]
__device__ float g_a1 [BB*HH*CC];       // [b][h][c]
__device__ float g_a2t[BB*WW*CC];       // [b][w][c]  (transposed for coalesced read)
__device__ float g_a3 [BB*HH*WW];       // [b][h][w]
__device__ float g_gpart[BB*HH*CC];     // per-(b,h) partial sums of s over w
__device__ float g_cw[BB*CC];           // SE channel gate

// ---------------- pool over W (pool1) and over C (pool3), one x read -------------
__global__ void pool13_kernel(const float* __restrict__ x) {
    int bh = blockIdx.x;                      // b*H + h
    const float* xp = x + (size_t)bh * (WW*CC);
    int c = threadIdx.x;

    // pool1: per-thread c, reduce over w (coalesced 1KB lines)
    float mx = -FLT_MAX, sm = 0.f;
    #pragma unroll 8
    for (int w = 0; w < WW; ++w) {
        float v = xp[w*CC + c];
        mx = fmaxf(mx, v); sm += v;
    }
    int o1 = (bh*CC + c)*2;
    g_pool1[o1]   = mx;
    g_pool1[o1+1] = sm * (1.f/WW);

    // pool3: warp per w, lanes stride over c (L1 hits after phase 1)
    int warp = threadIdx.x >> 5, lane = threadIdx.x & 31;
    for (int w = warp; w < WW; w += 8) {
        float m = -FLT_MAX, s = 0.f;
        #pragma unroll
        for (int cc = lane; cc < CC; cc += 32) {
            float v = xp[w*CC + cc];
            m = fmaxf(m, v); s += v;
        }
        #pragma unroll
        for (int off = 16; off; off >>= 1) {
            m = fmaxf(m, __shfl_xor_sync(0xFFFFFFFFu, m, off));
            s += __shfl_xor_sync(0xFFFFFFFFu, s, off);
        }
        if (lane == 0) {
            int o = (bh*WW + w)*2;
            g_pool3[o]   = m;
            g_pool3[o+1] = s * (1.f/CC);
        }
    }
}

// ---------------- pool over H (pool2) -------------------------------------------
__global__ void pool2_kernel(const float* __restrict__ x) {
    int bw = blockIdx.x;                      // b*W + w
    int b = bw / WW, w = bw % WW;
    int c = threadIdx.x;
    const float* xp = x + ((size_t)b*HW + w)*CC + c;
    float mx = -FLT_MAX, sm = 0.f;
    #pragma unroll 8
    for (int h = 0; h < HH; ++h) {
        float v = xp[(size_t)h*WW*CC];
        mx = fmaxf(mx, v); sm += v;
    }
    int o = ((b*CC + c)*WW + w)*2;
    g_pool2[o]   = mx;
    g_pool2[o+1] = sm * (1.f/HH);
}

// ---------------- 7x7 conv (2ch -> 1) + BN(inference) + sigmoid ------------------
// mode 0: out[(b*Hc+i)*Wc+j]   mode 1 (transposed): out[(b*Wc+j)*Hc+i]
__global__ void conv_bn_sig_kernel(const float* __restrict__ in, float* __restrict__ out,
                                   int Hc, int Wc, int mode,
                                   const float* __restrict__ wconv,
                                   const float* __restrict__ bias,
                                   const float* __restrict__ bng,
                                   const float* __restrict__ bnb,
                                   const float* __restrict__ bnm,
                                   const float* __restrict__ bnv) {
    __shared__ float ws[98];
    __shared__ float s_sc, s_sh, s_bs;
    if (threadIdx.x < 98) ws[threadIdx.x] = wconv[threadIdx.x];
    if (threadIdx.x == 0) {
        float sc = bng[0] * rsqrtf(bnv[0] + 1e-3f);
        s_sc = sc;
        s_sh = bnb[0] - bnm[0]*sc;
        s_bs = bias[0];
    }
    __syncthreads();

    int b = blockIdx.y;
    int idx = blockIdx.x*blockDim.x + threadIdx.x;
    if (idx >= Hc*Wc) return;
    int i = idx / Wc, j = idx % Wc;
    const float* inb = in + (size_t)b*Hc*Wc*2;

    float acc = s_bs;
    #pragma unroll
    for (int kh = 0; kh < 7; ++kh) {
        int i2 = i + kh - 3;
        if (i2 < 0 || i2 >= Hc) continue;
        #pragma unroll
        for (int kw = 0; kw < 7; ++kw) {
            int j2 = j + kw - 3;
            if (j2 < 0 || j2 >= Wc) continue;
            const float* p = inb + ((size_t)i2*Wc + j2)*2;
            acc += p[0]*ws[(kh*7+kw)*2] + p[1]*ws[(kh*7+kw)*2+1];
        }
    }
    float y = acc*s_sc + s_sh;
    float a = 1.f / (1.f + expf(-y));
    size_t o = mode ? ((size_t)b*Wc + j)*Hc + i
                    : ((size_t)b*Hc + i)*Wc + j;
    out[o] = a;
}

// ---------------- gap partials: sum_w x*(a1+a2+a3), per (b,h,c) ------------------
__global__ void gap_kernel(const float* __restrict__ x) {
    int bh = blockIdx.x;
    int b = bh / HH;
    int c = threadIdx.x;
    const float* xp  = x + (size_t)bh*(WW*CC) + c;
    const float* a2p = g_a2t + (size_t)b*WW*CC + c;
    const float* a3p = g_a3 + bh*WW;
    float ra1 = g_a1[bh*CC + c];
    float acc = 0.f;
    #pragma unroll 8
    for (int w = 0; w < WW; ++w) {
        float fac = ra1 + a2p[w*CC] + a3p[w];
        acc += xp[w*CC] * fac;
    }
    g_gpart[bh*CC + c] = acc;
}

// ---------------- SE MLP: 256 -> 32 (relu) -> 256 (sigmoid) ----------------------
__global__ void se_kernel(const float* __restrict__ w1, const float* __restrict__ b1,
                          const float* __restrict__ w2, const float* __restrict__ b2) {
    int b = blockIdx.x;
    int t = threadIdx.x;
    __shared__ float g[CC];
    __shared__ float hbuf[32];
    float s = 0.f;
    #pragma unroll 8
    for (int h = 0; h < HH; ++h) s += g_gpart[((size_t)b*HH + h)*CC + t];
    g[t] = s * (1.f/(HH*WW));
    __syncthreads();
    if (t < 32) {
        float a = b1[t];
        #pragma unroll 8
        for (int c = 0; c < CC; ++c) a += g[c]*w1[c*32 + t];
        hbuf[t] = fmaxf(a, 0.f);
    }
    __syncthreads();
    float a = b2[t];
    #pragma unroll
    for (int d = 0; d < 32; ++d) a += hbuf[d]*w2[d*CC + t];
    g_cw[b*CC + t] = 1.f / (1.f + expf(-a));
}

// ---------------- final: out = x * (a1+a2+a3) * cw -------------------------------
__global__ void final_kernel(const float* __restrict__ x, float* __restrict__ out) {
    int bh = blockIdx.x;
    int b = bh / HH;
    int c = threadIdx.x;
    size_t base = (size_t)bh*(WW*CC) + c;
    const float* a2p = g_a2t + (size_t)b*WW*CC + c;
    const float* a3p = g_a3 + bh*WW;
    float ra1 = g_a1[bh*CC + c];
    float rcw = g_cw[b*CC + c];
    #pragma unroll 8
    for (int w = 0; w < WW; ++w) {
        float fac = ra1 + a2p[w*CC] + a3p[w];
        out[base + w*CC] = x[base + w*CC] * fac * rcw;
    }
}

// ---------------- launch ----------------------------------------------------------
extern "C" void kernel_launch(void* const* d_in, const int* in_sizes, int n_in,
                              void* d_out, int out_size) {
    const float* x   = (const float*)d_in[0];
    const float* c1w = (const float*)d_in[1];
    const float* c1b = (const float*)d_in[2];
    const float* b1g = (const float*)d_in[3];
    const float* b1b = (const float*)d_in[4];
    const float* b1m = (const float*)d_in[5];
    const float* b1v = (const float*)d_in[6];
    const float* c2w = (const float*)d_in[7];
    const float* c2b = (const float*)d_in[8];
    const float* b2g = (const float*)d_in[9];
    const float* b2b = (const float*)d_in[10];
    const float* b2m = (const float*)d_in[11];
    const float* b2v = (const float*)d_in[12];
    const float* c3w = (const float*)d_in[13];
    const float* c3b = (const float*)d_in[14];
    const float* b3g = (const float*)d_in[15];
    const float* b3b = (const float*)d_in[16];
    const float* b3m = (const float*)d_in[17];
    const float* b3v = (const float*)d_in[18];
    const float* sw1 = (const float*)d_in[19];
    const float* sb1 = (const float*)d_in[20];
    const float* sw2 = (const float*)d_in[21];
    const float* sb2 = (const float*)d_in[22];
    float* out = (float*)d_out;

    void *p1, *p2, *p3, *a1, *a2t, *a3;
    cudaGetSymbolAddress(&p1,  g_pool1);
    cudaGetSymbolAddress(&p2,  g_pool2);
    cudaGetSymbolAddress(&p3,  g_pool3);
    cudaGetSymbolAddress(&a1,  g_a1);
    cudaGetSymbolAddress(&a2t, g_a2t);
    cudaGetSymbolAddress(&a3,  g_a3);

    pool13_kernel<<<BB*HH, CC>>>(x);
    pool2_kernel <<<BB*WW, CC>>>(x);

    // a1: grid (H=56 rows, C=256 cols) -> normal layout [b][h][c]
    conv_bn_sig_kernel<<<dim3(56, BB), 256>>>((const float*)p1, (float*)a1,
        HH, CC, 0, c1w, c1b, b1g, b1b, b1m, b1v);
    // a2: grid (C=256 rows, W=56 cols) -> transposed store [b][w][c]
    conv_bn_sig_kernel<<<dim3(56, BB), 256>>>((const float*)p2, (float*)a2t,
        CC, WW, 1, c2w, c2b, b2g, b2b, b2m, b2v);
    // a3: grid (H=56, W=56) -> [b][h][w]
    conv_bn_sig_kernel<<<dim3(13, BB), 256>>>((const float*)p3, (float*)a3,
        HH, WW, 0, c3w, c3b, b3g, b3b, b3m, b3v);

    gap_kernel<<<BB*HH, CC>>>(x);
    se_kernel<<<BB, CC>>>(sw1, sb1, sw2, sb2);
    final_kernel<<<BB*HH, CC>>>(x, out);
}

// round 2
// speedup vs baseline: 1.2124x; 1.2124x over previous
#include <cuda_runtime.h>
#include <math.h>
#include <float.h>

#define BB 32
#define HH 56
#define WW 56
#define CC 256
#define HW (HH*WW)

// ---------------- scratch (device globals; 16B aligned for vector access) --------
__device__ __align__(16) float g_pool1[BB*HH*CC*2];   // [b][h][c][{max,mean}]
__device__ __align__(16) float g_pool2[BB*CC*WW*2];   // [b][c][w][{max,mean}]
__device__ __align__(16) float g_pool3[BB*HH*WW*2];   // [b][h][w][{max,mean}]
__device__ __align__(16) float g_a1 [BB*HH*CC];       // [b][h][c]
__device__ __align__(16) float g_a2t[BB*WW*CC];       // [b][w][c]
__device__ __align__(16) float g_a3 [BB*HH*WW];       // [b][h][w]
__device__ __align__(16) float g_gpart[BB*HH*CC];     // per-(b,h) partial sums
__device__ __align__(16) float g_cw[BB*CC];           // SE channel gate

__device__ __forceinline__ float4 f4max(float4 a, float4 b) {
    return make_float4(fmaxf(a.x,b.x), fmaxf(a.y,b.y), fmaxf(a.z,b.z), fmaxf(a.w,b.w));
}

// ---------------- pool over W (pool1) and over C (pool3), one x read -------------
__global__ void pool13_kernel(const float* __restrict__ x) {
    int bh = blockIdx.x;
    const float* xp = x + (size_t)bh * (WW*CC);
    int t = threadIdx.x;
    int w4 = t >> 6, c4 = t & 63;

    // pool1: 4 w-groups x 64 c-quads, float4 loads
    float4 mx = make_float4(-FLT_MAX,-FLT_MAX,-FLT_MAX,-FLT_MAX);
    float4 sm = make_float4(0.f,0.f,0.f,0.f);
    #pragma unroll
    for (int w = w4; w < WW; w += 4) {
        float4 v = *(const float4*)(xp + w*CC + c4*4);
        mx = f4max(mx, v);
        sm.x += v.x; sm.y += v.y; sm.z += v.z; sm.w += v.w;
    }
    __shared__ float4 smx[4][64], ssm[4][64];
    smx[w4][c4] = mx; ssm[w4][c4] = sm;
    __syncthreads();
    if (t < 64) {
        float4 m = smx[0][t], s = ssm[0][t];
        #pragma unroll
        for (int g = 1; g < 4; ++g) {
            m = f4max(m, smx[g][t]);
            float4 q = ssm[g][t];
            s.x += q.x; s.y += q.y; s.z += q.z; s.w += q.w;
        }
        const float inv = 1.f/WW;
        float4* o = (float4*)(g_pool1 + (size_t)bh*CC*2) + t*2;
        o[0] = make_float4(m.x, s.x*inv, m.y, s.y*inv);
        o[1] = make_float4(m.z, s.z*inv, m.w, s.w*inv);
    }

    // pool3: warp per w, float4 lanes over c (L1 hits)
    int warp = t >> 5, lane = t & 31;
    #pragma unroll
    for (int w = warp; w < WW; w += 8) {
        const float4* p = (const float4*)(xp + w*CC);
        float4 a = p[lane], b = p[lane + 32];
        float m = fmaxf(fmaxf(fmaxf(a.x,a.y),fmaxf(a.z,a.w)),
                        fmaxf(fmaxf(b.x,b.y),fmaxf(b.z,b.w)));
        float s = a.x+a.y+a.z+a.w + b.x+b.y+b.z+b.w;
        #pragma unroll
        for (int off = 16; off; off >>= 1) {
            m = fmaxf(m, __shfl_xor_sync(0xFFFFFFFFu, m, off));
            s += __shfl_xor_sync(0xFFFFFFFFu, s, off);
        }
        if (lane == 0) {
            int o = (bh*WW + w)*2;
            g_pool3[o]   = m;
            g_pool3[o+1] = s * (1.f/CC);
        }
    }
}

// ---------------- pool over H (pool2) -------------------------------------------
__global__ void pool2_kernel(const float* __restrict__ x) {
    int bw = blockIdx.x;
    int b = bw / WW, w = bw % WW;
    int t = threadIdx.x;
    int h4 = t >> 6, c4 = t & 63;
    const float* xp = x + ((size_t)b*HW + w)*CC + c4*4;
    float4 mx = make_float4(-FLT_MAX,-FLT_MAX,-FLT_MAX,-FLT_MAX);
    float4 sm = make_float4(0.f,0.f,0.f,0.f);
    #pragma unroll
    for (int h = h4; h < HH; h += 4) {
        float4 v = *(const float4*)(xp + (size_t)h*WW*CC);
        mx = f4max(mx, v);
        sm.x += v.x; sm.y += v.y; sm.z += v.z; sm.w += v.w;
    }
    __shared__ float4 smx[4][64], ssm[4][64];
    smx[h4][c4] = mx; ssm[h4][c4] = sm;
    __syncthreads();
    if (t < 64) {
        float4 m = smx[0][t], s = ssm[0][t];
        #pragma unroll
        for (int g = 1; g < 4; ++g) {
            m = f4max(m, smx[g][t]);
            float4 q = ssm[g][t];
            s.x += q.x; s.y += q.y; s.z += q.z; s.w += q.w;
        }
        const float inv = 1.f/HH;
        // g_pool2[b][c][w]{max,mean}, c = 4t..4t+3
        float2* o = (float2*)g_pool2 + ((size_t)b*CC + t*4)*WW + w;
        o[0]      = make_float2(m.x, s.x*inv);
        o[WW]     = make_float2(m.y, s.y*inv);
        o[2*WW]   = make_float2(m.z, s.z*inv);
        o[3*WW]   = make_float2(m.w, s.w*inv);
    }
}

// ---------------- 7x7 conv (2ch->1) + BN + sigmoid, smem-tiled, branchless -------
template<int HC, int WC, int MODE>
__device__ __forceinline__ void do_conv(
    float2* tile, float2* wsm,
    const float* __restrict__ in, float* __restrict__ out,
    int b, int t0, float sc, float sh, float bs)
{
    const int TI = 8;
    const int PW = WC + 6;
    int tid = threadIdx.x;
    int i0 = t0 * TI;

    // cooperative padded load (both channels as float2)
    const float2* inb = (const float2*)in + (size_t)b*HC*WC;
    for (int idx = tid; idx < (TI+6)*PW; idx += 256) {
        int r = idx / PW, col = idx - r*PW;
        int i2 = i0 + r - 3, j2 = col - 3;
        float2 v = make_float2(0.f, 0.f);
        if (i2 >= 0 && i2 < HC && j2 >= 0 && j2 < WC)
            v = inb[i2*WC + j2];
        tile[idx] = v;
    }
    __syncthreads();

    for (int o = tid; o < TI*WC; o += 256) {
        int r = o / WC, j = o - r*WC;
        const float2* base = tile + r*PW + j;
        float acc = bs;
        #pragma unroll
        for (int kh = 0; kh < 7; ++kh) {
            #pragma unroll
            for (int kw = 0; kw < 7; ++kw) {
                float2 v = base[kh*PW + kw];
                float2 w = wsm[kh*7 + kw];
                acc = fmaf(v.x, w.x, acc);
                acc = fmaf(v.y, w.y, acc);
            }
        }
        float y = acc*sc + sh;
        float a = 1.f / (1.f + __expf(-y));
        int i = i0 + r;
        size_t oo = MODE ? ((size_t)b*WC + j)*HC + i
                         : ((size_t)b*HC + i)*WC + j;
        out[oo] = a;
    }
}

__global__ void conv_all_kernel(
    const float* __restrict__ c1w, const float* __restrict__ c1b,
    const float* __restrict__ b1g, const float* __restrict__ b1b,
    const float* __restrict__ b1m, const float* __restrict__ b1v,
    const float* __restrict__ c2w, const float* __restrict__ c2b,
    const float* __restrict__ b2g, const float* __restrict__ b2b,
    const float* __restrict__ b2m, const float* __restrict__ b2v,
    const float* __restrict__ c3w, const float* __restrict__ c3b,
    const float* __restrict__ b3g, const float* __restrict__ b3b,
    const float* __restrict__ b3m, const float* __restrict__ b3v)
{
    __shared__ float2 tile[14*262];   // max: (8+6) x (256+6)
    __shared__ float2 wsm[49];

    int bx = blockIdx.x;
    int which, b, t0;
    const float *wc, *bc, *bg, *bb, *bm, *bv;
    if (bx < 224)        { which = 0; int r = bx;        b = r/7;  t0 = r%7;
                           wc=c1w; bc=c1b; bg=b1g; bb=b1b; bm=b1m; bv=b1v; }
    else if (bx < 1248)  { which = 1; int r = bx - 224;  b = r/32; t0 = r%32;
                           wc=c2w; bc=c2b; bg=b2g; bb=b2b; bm=b2m; bv=b2v; }
    else                 { which = 2; int r = bx - 1248; b = r/7;  t0 = r%7;
                           wc=c3w; bc=c3b; bg=b3g; bb=b3b; bm=b3m; bv=b3v; }

    if (threadIdx.x < 49) wsm[threadIdx.x] = ((const float2*)wc)[threadIdx.x];
    float sc = bg[0] * rsqrtf(bv[0] + 1e-3f);
    float sh = bb[0] - bm[0]*sc;
    float bs = bc[0];
    __syncthreads();

    if (which == 0)
        do_conv<HH, CC, 0>(tile, wsm, g_pool1, g_a1,  b, t0, sc, sh, bs);
    else if (which == 1)
        do_conv<CC, WW, 1>(tile, wsm, g_pool2, g_a2t, b, t0, sc, sh, bs);
    else
        do_conv<HH, WW, 0>(tile, wsm, g_pool3, g_a3,  b, t0, sc, sh, bs);
}

// ---------------- gap partials: sum_w x*(a1+a2+a3), per (b,h,c) ------------------
__global__ void gap_kernel(const float* __restrict__ x) {
    int bh = blockIdx.x;
    int b = bh / HH;
    int t = threadIdx.x;
    int w4 = t >> 6, c4 = t & 63;
    const float* xp  = x + (size_t)bh*(WW*CC) + c4*4;
    const float* a2p = g_a2t + (size_t)b*WW*CC + c4*4;
    const float* a3p = g_a3 + bh*WW;
    float4 ra1 = *((const float4*)(g_a1 + (size_t)bh*CC) + c4);
    float4 acc = make_float4(0.f,0.f,0.f,0.f);
    #pragma unroll
    for (int w = w4; w < WW; w += 4) {
        float4 xv = *(const float4*)(xp + w*CC);
        float4 a2 = *(const float4*)(a2p + w*CC);
        float a3 = a3p[w];
        acc.x = fmaf(xv.x, ra1.x + a2.x + a3, acc.x);
        acc.y = fmaf(xv.y, ra1.y + a2.y + a3, acc.y);
        acc.z = fmaf(xv.z, ra1.z + a2.z + a3, acc.z);
        acc.w = fmaf(xv.w, ra1.w + a2.w + a3, acc.w);
    }
    __shared__ float4 sa[4][64];
    sa[w4][c4] = acc;
    __syncthreads();
    if (t < 64) {
        float4 s = sa[0][t];
        #pragma unroll
        for (int g = 1; g < 4; ++g) {
            float4 q = sa[g][t];
            s.x += q.x; s.y += q.y; s.z += q.z; s.w += q.w;
        }
        ((float4*)(g_gpart + (size_t)bh*CC))[t] = s;
    }
}

// ---------------- SE MLP: 256 -> 32 (relu) -> 256 (sigmoid) ----------------------
__global__ void se_kernel(const float* __restrict__ w1, const float* __restrict__ b1,
                          const float* __restrict__ w2, const float* __restrict__ b2) {
    int b = blockIdx.x;
    int t = threadIdx.x;
    __shared__ float g[CC];
    __shared__ float hbuf[32];
    float s = 0.f;
    #pragma unroll 8
    for (int h = 0; h < HH; ++h) s += g_gpart[((size_t)b*HH + h)*CC + t];
    g[t] = s * (1.f/(HH*WW));
    __syncthreads();
    if (t < 32) {
        float a = b1[t];
        #pragma unroll 8
        for (int c = 0; c < CC; ++c) a = fmaf(g[c], w1[c*32 + t], a);
        hbuf[t] = fmaxf(a, 0.f);
    }
    __syncthreads();
    float a = b2[t];
    #pragma unroll
    for (int d = 0; d < 32; ++d) a = fmaf(hbuf[d], w2[d*CC + t], a);
    g_cw[b*CC + t] = 1.f / (1.f + __expf(-a));
}

// ---------------- final: out = x * (a1+a2+a3) * cw -------------------------------
__global__ void final_kernel(const float* __restrict__ x, float* __restrict__ out) {
    int bh = blockIdx.x;
    int b = bh / HH;
    int t = threadIdx.x;
    int w4 = t >> 6, c4 = t & 63;
    size_t base = (size_t)bh*(WW*CC) + c4*4;
    const float* a2p = g_a2t + (size_t)b*WW*CC + c4*4;
    const float* a3p = g_a3 + bh*WW;
    float4 ra1 = *((const float4*)(g_a1 + (size_t)bh*CC) + c4);
    float4 rcw = *((const float4*)(g_cw + (size_t)b*CC) + c4);
    #pragma unroll
    for (int w = w4; w < WW; w += 4) {
        float4 xv = *(const float4*)(x + base + w*CC);
        float4 a2 = *(const float4*)(a2p + w*CC);
        float a3 = a3p[w];
        float4 o;
        o.x = xv.x * (ra1.x + a2.x + a3) * rcw.x;
        o.y = xv.y * (ra1.y + a2.y + a3) * rcw.y;
        o.z = xv.z * (ra1.z + a2.z + a3) * rcw.z;
        o.w = xv.w * (ra1.w + a2.w + a3) * rcw.w;
        *(float4*)(out + base + w*CC) = o;
    }
}

// ---------------- launch ----------------------------------------------------------
extern "C" void kernel_launch(void* const* d_in, const int* in_sizes, int n_in,
                              void* d_out, int out_size) {
    const float* x   = (const float*)d_in[0];
    const float* c1w = (const float*)d_in[1];
    const float* c1b = (const float*)d_in[2];
    const float* b1g = (const float*)d_in[3];
    const float* b1b = (const float*)d_in[4];
    const float* b1m = (const float*)d_in[5];
    const float* b1v = (const float*)d_in[6];
    const float* c2w = (const float*)d_in[7];
    const float* c2b = (const float*)d_in[8];
    const float* b2g = (const float*)d_in[9];
    const float* b2b = (const float*)d_in[10];
    const float* b2m = (const float*)d_in[11];
    const float* b2v = (const float*)d_in[12];
    const float* c3w = (const float*)d_in[13];
    const float* c3b = (const float*)d_in[14];
    const float* b3g = (const float*)d_in[15];
    const float* b3b = (const float*)d_in[16];
    const float* b3m = (const float*)d_in[17];
    const float* b3v = (const float*)d_in[18];
    const float* sw1 = (const float*)d_in[19];
    const float* sb1 = (const float*)d_in[20];
    const float* sw2 = (const float*)d_in[21];
    const float* sb2 = (const float*)d_in[22];
    float* out = (float*)d_out;

    pool13_kernel<<<BB*HH, 256>>>(x);
    pool2_kernel <<<BB*WW, 256>>>(x);

    conv_all_kernel<<<1472, 256>>>(
        c1w, c1b, b1g, b1b, b1m, b1v,
        c2w, c2b, b2g, b2b, b2m, b2v,
        c3w, c3b, b3g, b3b, b3m, b3v);

    gap_kernel<<<BB*HH, 256>>>(x);
    se_kernel<<<BB, CC>>>(sw1, sb1, sw2, sb2);
    final_kernel<<<BB*HH, 256>>>(x, out);
}

// round 3
// speedup vs baseline: 1.2295x; 1.0142x over previous
#include <cuda_runtime.h>
#include <math.h>
#include <float.h>

#define BB 32
#define HH 56
#define WW 56
#define CC 256
#define HW (HH*WW)
#define NB (BB*14)   // 448 blocks per streaming pass (4 rows x 64 c-quads each)

// ---------------- scratch (device globals) ---------------------------------------
__device__ __align__(16) float g_pool1[BB*HH*CC*2];   // [b][h][c][{max,mean}]
__device__ __align__(16) float g_pool2[BB*CC*WW*2];   // [b][c][w][{max,mean}]
__device__ __align__(16) float g_pool3[BB*HH*WW*2];   // [b][h][w][{max,mean}]
__device__ __align__(16) float g_a1 [BB*HH*CC];       // [b][h][c]
__device__ __align__(16) float g_a2t[BB*WW*CC];       // [b][w][c]
__device__ __align__(16) float g_a3 [BB*HH*WW];       // [b][h][w]
__device__ __align__(16) float g_gpart[BB*HH*CC];     // per-(b,h) partial sums
__device__ __align__(16) float g_cw[BB*CC];           // SE channel gate

__device__ __forceinline__ float4 f4max(float4 a, float4 b) {
    return make_float4(fmaxf(a.x,b.x), fmaxf(a.y,b.y), fmaxf(a.z,b.z), fmaxf(a.w,b.w));
}

// ---------------- all three pools, one kernel ------------------------------------
// blocks [0, NB):   pool1 + pool3  (block = (b, h-quad); thread = (h_local, c4))
// blocks [NB, 2NB): pool2          (block = (b, w-quad); thread = (w_local, c4))
__global__ __launch_bounds__(256) void pools_kernel(const float* __restrict__ x) {
    int t = threadIdx.x;
    int sub = t >> 6;          // 0..3
    int c4  = t & 63;          // c-quad index

    if (blockIdx.x < NB) {
        int b = blockIdx.x / 14, hq = blockIdx.x % 14;
        int h = hq*4 + sub;
        int bh = b*HH + h;
        const float* xp = x + (size_t)bh*(WW*CC) + c4*4;

        int lane = t & 31;
        int half = c4 >> 5;                    // which 128-channel half
        __shared__ float2 s3[4][WW][2];        // pool3 partials (max,sum)

        float4 mx = make_float4(-FLT_MAX,-FLT_MAX,-FLT_MAX,-FLT_MAX);
        float4 sm = make_float4(0.f,0.f,0.f,0.f);
        #pragma unroll 8
        for (int w = 0; w < WW; ++w) {
            float4 v = *(const float4*)(xp + w*CC);
            mx = f4max(mx, v);
            sm.x += v.x; sm.y += v.y; sm.z += v.z; sm.w += v.w;
            // pool3 contribution: reduce this warp's 128 channels
            float m = fmaxf(fmaxf(v.x,v.y), fmaxf(v.z,v.w));
            float s = v.x+v.y+v.z+v.w;
            #pragma unroll
            for (int off = 16; off; off >>= 1) {
                m = fmaxf(m, __shfl_xor_sync(0xFFFFFFFFu, m, off));
                s += __shfl_xor_sync(0xFFFFFFFFu, s, off);
            }
            if (lane == 0) s3[sub][w][half] = make_float2(m, s);
        }
        // pool1 write (per-thread, no reduction needed)
        {
            const float invw = 1.f/WW;
            float4* o = (float4*)(g_pool1 + ((size_t)bh*CC + c4*4)*2);
            o[0] = make_float4(mx.x, sm.x*invw, mx.y, sm.y*invw);
            o[1] = make_float4(mx.z, sm.z*invw, mx.w, sm.w*invw);
        }
        __syncthreads();
        // pool3 finalize: 4*56 = 224 outputs
        if (t < 224) {
            int hl = t / WW, w = t % WW;
            float2 p0 = s3[hl][w][0], p1 = s3[hl][w][1];
            int o = ((b*HH + hq*4 + hl)*WW + w)*2;
            g_pool3[o]   = fmaxf(p0.x, p1.x);
            g_pool3[o+1] = (p0.y + p1.y) * (1.f/CC);
        }
    } else {
        int blk = blockIdx.x - NB;
        int b = blk / 14, wq = blk % 14;
        int w = wq*4 + sub;
        const float* xp = x + ((size_t)b*HW + w)*CC + c4*4;
        float4 mx = make_float4(-FLT_MAX,-FLT_MAX,-FLT_MAX,-FLT_MAX);
        float4 sm = make_float4(0.f,0.f,0.f,0.f);
        #pragma unroll 8
        for (int h = 0; h < HH; ++h) {
            float4 v = *(const float4*)(xp + (size_t)h*WW*CC);
            mx = f4max(mx, v);
            sm.x += v.x; sm.y += v.y; sm.z += v.z; sm.w += v.w;
        }
        const float invh = 1.f/HH;
        float2* o = (float2*)g_pool2 + ((size_t)b*CC + c4*4)*WW + w;
        o[0]    = make_float2(mx.x, sm.x*invh);
        o[WW]   = make_float2(mx.y, sm.y*invh);
        o[2*WW] = make_float2(mx.z, sm.z*invh);
        o[3*WW] = make_float2(mx.w, sm.w*invh);
    }
}

// ---------------- 7x7 conv (2ch->1) + BN + sigmoid, smem-tiled, branchless -------
template<int HC, int WC, int MODE>
__device__ __forceinline__ void do_conv(
    float2* tile, float2* wsm,
    const float* __restrict__ in, float* __restrict__ out,
    int b, int t0, float sc, float sh, float bs)
{
    const int TI = 8;
    const int PW = WC + 6;
    int tid = threadIdx.x;
    int i0 = t0 * TI;

    const float2* inb = (const float2*)in + (size_t)b*HC*WC;
    for (int idx = tid; idx < (TI+6)*PW; idx += 256) {
        int r = idx / PW, col = idx - r*PW;
        int i2 = i0 + r - 3, j2 = col - 3;
        float2 v = make_float2(0.f, 0.f);
        if (i2 >= 0 && i2 < HC && j2 >= 0 && j2 < WC)
            v = inb[i2*WC + j2];
        tile[idx] = v;
    }
    __syncthreads();

    for (int o = tid; o < TI*WC; o += 256) {
        int r = o / WC, j = o - r*WC;
        const float2* base = tile + r*PW + j;
        float acc = bs;
        #pragma unroll
        for (int kh = 0; kh < 7; ++kh) {
            #pragma unroll
            for (int kw = 0; kw < 7; ++kw) {
                float2 v = base[kh*PW + kw];
                float2 w = wsm[kh*7 + kw];
                acc = fmaf(v.x, w.x, acc);
                acc = fmaf(v.y, w.y, acc);
            }
        }
        float y = acc*sc + sh;
        float a = 1.f / (1.f + __expf(-y));
        int i = i0 + r;
        size_t oo = MODE ? ((size_t)b*WC + j)*HC + i
                         : ((size_t)b*HC + i)*WC + j;
        out[oo] = a;
    }
}

__global__ void conv_all_kernel(
    const float* __restrict__ c1w, const float* __restrict__ c1b,
    const float* __restrict__ b1g, const float* __restrict__ b1b,
    const float* __restrict__ b1m, const float* __restrict__ b1v,
    const float* __restrict__ c2w, const float* __restrict__ c2b,
    const float* __restrict__ b2g, const float* __restrict__ b2b,
    const float* __restrict__ b2m, const float* __restrict__ b2v,
    const float* __restrict__ c3w, const float* __restrict__ c3b,
    const float* __restrict__ b3g, const float* __restrict__ b3b,
    const float* __restrict__ b3m, const float* __restrict__ b3v)
{
    __shared__ float2 tile[14*262];
    __shared__ float2 wsm[49];

    int bx = blockIdx.x;
    int which, b, t0;
    const float *wc, *bc, *bg, *bb, *bm, *bv;
    if (bx < 224)        { which = 0; int r = bx;        b = r/7;  t0 = r%7;
                           wc=c1w; bc=c1b; bg=b1g; bb=b1b; bm=b1m; bv=b1v; }
    else if (bx < 1248)  { which = 1; int r = bx - 224;  b = r/32; t0 = r%32;
                           wc=c2w; bc=c2b; bg=b2g; bb=b2b; bm=b2m; bv=b2v; }
    else                 { which = 2; int r = bx - 1248; b = r/7;  t0 = r%7;
                           wc=c3w; bc=c3b; bg=b3g; bb=b3b; bm=b3m; bv=b3v; }

    if (threadIdx.x < 49) wsm[threadIdx.x] = ((const float2*)wc)[threadIdx.x];
    float sc = bg[0] * rsqrtf(bv[0] + 1e-3f);
    float sh = bb[0] - bm[0]*sc;
    float bs = bc[0];
    __syncthreads();

    if (which == 0)
        do_conv<HH, CC, 0>(tile, wsm, g_pool1, g_a1,  b, t0, sc, sh, bs);
    else if (which == 1)
        do_conv<CC, WW, 1>(tile, wsm, g_pool2, g_a2t, b, t0, sc, sh, bs);
    else
        do_conv<HH, WW, 0>(tile, wsm, g_pool3, g_a3,  b, t0, sc, sh, bs);
}

// ---------------- gap partials: sum_w x*(a1+a2+a3), per (b,h,c) ------------------
__global__ __launch_bounds__(256) void gap_kernel(const float* __restrict__ x) {
    int t = threadIdx.x;
    int sub = t >> 6, c4 = t & 63;
    int b = blockIdx.x / 14, hq = blockIdx.x % 14;
    int h = hq*4 + sub;
    int bh = b*HH + h;
    const float* xp  = x + (size_t)bh*(WW*CC) + c4*4;
    const float* a2p = g_a2t + (size_t)b*WW*CC + c4*4;
    const float* a3p = g_a3 + bh*WW;
    float4 ra1 = *((const float4*)(g_a1 + (size_t)bh*CC) + c4);
    float4 acc = make_float4(0.f,0.f,0.f,0.f);
    #pragma unroll 8
    for (int w = 0; w < WW; ++w) {
        float4 xv = *(const float4*)(xp + w*CC);
        float4 a2 = *(const float4*)(a2p + w*CC);
        float a3 = a3p[w];
        acc.x = fmaf(xv.x, ra1.x + a2.x + a3, acc.x);
        acc.y = fmaf(xv.y, ra1.y + a2.y + a3, acc.y);
        acc.z = fmaf(xv.z, ra1.z + a2.z + a3, acc.z);
        acc.w = fmaf(xv.w, ra1.w + a2.w + a3, acc.w);
    }
    *((float4*)(g_gpart + (size_t)bh*CC) + c4) = acc;
}

// ---------------- SE MLP: 256 -> 32 (relu) -> 256 (sigmoid) ----------------------
__global__ void se_kernel(const float* __restrict__ w1, const float* __restrict__ b1,
                          const float* __restrict__ w2, const float* __restrict__ b2) {
    int b = blockIdx.x;
    int t = threadIdx.x;
    __shared__ float g[CC];
    __shared__ float hbuf[32];
    float s = 0.f;
    #pragma unroll 8
    for (int h = 0; h < HH; ++h) s += g_gpart[((size_t)b*HH + h)*CC + t];
    g[t] = s * (1.f/(HH*WW));
    __syncthreads();
    if (t < 32) {
        float a = b1[t];
        #pragma unroll 8
        for (int c = 0; c < CC; ++c) a = fmaf(g[c], w1[c*32 + t], a);
        hbuf[t] = fmaxf(a, 0.f);
    }
    __syncthreads();
    float a = b2[t];
    #pragma unroll
    for (int d = 0; d < 32; ++d) a = fmaf(hbuf[d], w2[d*CC + t], a);
    g_cw[b*CC + t] = 1.f / (1.f + __expf(-a));
}

// ---------------- final: out = x * (a1+a2+a3) * cw -------------------------------
__global__ __launch_bounds__(256) void final_kernel(const float* __restrict__ x,
                                                    float* __restrict__ out) {
    int t = threadIdx.x;
    int sub = t >> 6, c4 = t & 63;
    int b = blockIdx.x / 14, hq = blockIdx.x % 14;
    int h = hq*4 + sub;
    int bh = b*HH + h;
    size_t base = (size_t)bh*(WW*CC) + c4*4;
    const float* a2p = g_a2t + (size_t)b*WW*CC + c4*4;
    const float* a3p = g_a3 + bh*WW;
    float4 ra1 = *((const float4*)(g_a1 + (size_t)bh*CC) + c4);
    float4 rcw = *((const float4*)(g_cw + (size_t)b*CC) + c4);
    #pragma unroll 8
    for (int w = 0; w < WW; ++w) {
        float4 xv = *(const float4*)(x + base + w*CC);
        float4 a2 = *(const float4*)(a2p + w*CC);
        float a3 = a3p[w];
        float4 o;
        o.x = xv.x * (ra1.x + a2.x + a3) * rcw.x;
        o.y = xv.y * (ra1.y + a2.y + a3) * rcw.y;
        o.z = xv.z * (ra1.z + a2.z + a3) * rcw.z;
        o.w = xv.w * (ra1.w + a2.w + a3) * rcw.w;
        *(float4*)(out + base + w*CC) = o;
    }
}

// ---------------- launch ----------------------------------------------------------
extern "C" void kernel_launch(void* const* d_in, const int* in_sizes, int n_in,
                              void* d_out, int out_size) {
    const float* x   = (const float*)d_in[0];
    const float* c1w = (const float*)d_in[1];
    const float* c1b = (const float*)d_in[2];
    const float* b1g = (const float*)d_in[3];
    const float* b1b = (const float*)d_in[4];
    const float* b1m = (const float*)d_in[5];
    const float* b1v = (const float*)d_in[6];
    const float* c2w = (const float*)d_in[7];
    const float* c2b = (const float*)d_in[8];
    const float* b2g = (const float*)d_in[9];
    const float* b2b = (const float*)d_in[10];
    const float* b2m = (const float*)d_in[11];
    const float* b2v = (const float*)d_in[12];
    const float* c3w = (const float*)d_in[13];
    const float* c3b = (const float*)d_in[14];
    const float* b3g = (const float*)d_in[15];
    const float* b3b = (const float*)d_in[16];
    const float* b3m = (const float*)d_in[17];
    const float* b3v = (const float*)d_in[18];
    const float* sw1 = (const float*)d_in[19];
    const float* sb1 = (const float*)d_in[20];
    const float* sw2 = (const float*)d_in[21];
    const float* sb2 = (const float*)d_in[22];
    float* out = (float*)d_out;

    pools_kernel<<<2*NB, 256>>>(x);
    conv_all_kernel<<<1472, 256>>>(
        c1w, c1b, b1g, b1b, b1m, b1v,
        c2w, c2b, b2g, b2b, b2m, b2v,
        c3w, c3b, b3g, b3b, b3m, b3v);
    gap_kernel<<<NB, 256>>>(x);
    se_kernel<<<BB, CC>>>(sw1, sb1, sw2, sb2);
    final_kernel<<<NB, 256>>>(x, out);
}

// round 5
// speedup vs baseline: 1.2806x; 1.0415x over previous
#include <cuda_runtime.h>
#include <math.h>
#include <float.h>

#define BB 32
#define HH 56
#define WW 56
#define CC 256
#define HW (HH*WW)
#define NB (BB*14)   // 448 blocks per streaming pass (4 rows x 64 c-quads each)

// ---------------- scratch (device globals) ---------------------------------------
__device__ __align__(16) float g_pool1[BB*HH*CC*2];   // [b][h][c][{max,mean}]
__device__ __align__(16) float g_pool2[BB*CC*WW*2];   // [b][c][w][{max,mean}]
__device__ __align__(16) float g_pool3[BB*HH*WW*2];   // [b][h][w][{max,mean}]
__device__ __align__(16) float g_a1 [BB*HH*CC];       // [b][h][c]
__device__ __align__(16) float g_a2t[BB*WW*CC];       // [b][w][c]
__device__ __align__(16) float g_a3 [BB*HH*WW];       // [b][h][w]
__device__ __align__(16) float g_gpart[BB*HH*CC];     // per-(b,h) partial sums
__device__ __align__(16) float g_cw[BB*CC];           // SE channel gate

__device__ __forceinline__ float4 f4max(float4 a, float4 b) {
    return make_float4(fmaxf(a.x,b.x), fmaxf(a.y,b.y), fmaxf(a.z,b.z), fmaxf(a.w,b.w));
}

// ---------------- all three pools, one kernel ------------------------------------
__global__ __launch_bounds__(256) void pools_kernel(const float* __restrict__ x) {
    int t = threadIdx.x;
    int sub = t >> 6;          // 0..3
    int c4  = t & 63;          // c-quad index

    if (blockIdx.x < NB) {
        int b = blockIdx.x / 14, hq = blockIdx.x % 14;
        int h = hq*4 + sub;
        int bh = b*HH + h;
        const float* xp = x + (size_t)bh*(WW*CC) + c4*4;

        int lane = t & 31;
        int half = c4 >> 5;
        __shared__ float2 s3[4][WW][2];

        float4 mx = make_float4(-FLT_MAX,-FLT_MAX,-FLT_MAX,-FLT_MAX);
        float4 sm = make_float4(0.f,0.f,0.f,0.f);
        #pragma unroll 8
        for (int w = 0; w < WW; ++w) {
            float4 v = *(const float4*)(xp + w*CC);
            mx = f4max(mx, v);
            sm.x += v.x; sm.y += v.y; sm.z += v.z; sm.w += v.w;
            float m = fmaxf(fmaxf(v.x,v.y), fmaxf(v.z,v.w));
            float s = v.x+v.y+v.z+v.w;
            #pragma unroll
            for (int off = 16; off; off >>= 1) {
                m = fmaxf(m, __shfl_xor_sync(0xFFFFFFFFu, m, off));
                s += __shfl_xor_sync(0xFFFFFFFFu, s, off);
            }
            if (lane == 0) s3[sub][w][half] = make_float2(m, s);
        }
        {
            const float invw = 1.f/WW;
            float4* o = (float4*)(g_pool1 + ((size_t)bh*CC + c4*4)*2);
            o[0] = make_float4(mx.x, sm.x*invw, mx.y, sm.y*invw);
            o[1] = make_float4(mx.z, sm.z*invw, mx.w, sm.w*invw);
        }
        __syncthreads();
        if (t < 224) {
            int hl = t / WW, w = t % WW;
            float2 p0 = s3[hl][w][0], p1 = s3[hl][w][1];
            int o = ((b*HH + hq*4 + hl)*WW + w)*2;
            g_pool3[o]   = fmaxf(p0.x, p1.x);
            g_pool3[o+1] = (p0.y + p1.y) * (1.f/CC);
        }
    } else {
        int blk = blockIdx.x - NB;
        int b = blk / 14, wq = blk % 14;
        int w = wq*4 + sub;
        const float* xp = x + ((size_t)b*HW + w)*CC + c4*4;
        float4 mx = make_float4(-FLT_MAX,-FLT_MAX,-FLT_MAX,-FLT_MAX);
        float4 sm = make_float4(0.f,0.f,0.f,0.f);
        #pragma unroll 8
        for (int h = 0; h < HH; ++h) {
            float4 v = *(const float4*)(xp + (size_t)h*WW*CC);
            mx = f4max(mx, v);
            sm.x += v.x; sm.y += v.y; sm.z += v.z; sm.w += v.w;
        }
        const float invh = 1.f/HH;
        float2* o = (float2*)g_pool2 + ((size_t)b*CC + c4*4)*WW + w;
        o[0]    = make_float2(mx.x, sm.x*invh);
        o[WW]   = make_float2(mx.y, sm.y*invh);
        o[2*WW] = make_float2(mx.z, sm.z*invh);
        o[3*WW] = make_float2(mx.w, sm.w*invh);
    }
}

// ---------------- 7x7 conv (2ch->1) + BN + sigmoid, smem-tiled, branchless -------
template<int HC, int WC, int MODE>
__device__ __forceinline__ void do_conv(
    float2* tile, float2* wsm,
    const float* __restrict__ in, float* __restrict__ out,
    int b, int t0, float sc, float sh, float bs)
{
    const int TI = 8;
    const int PW = WC + 6;
    int tid = threadIdx.x;
    int i0 = t0 * TI;

    const float2* inb = (const float2*)in + (size_t)b*HC*WC;
    for (int idx = tid; idx < (TI+6)*PW; idx += 256) {
        int r = idx / PW, col = idx - r*PW;
        int i2 = i0 + r - 3, j2 = col - 3;
        float2 v = make_float2(0.f, 0.f);
        if (i2 >= 0 && i2 < HC && j2 >= 0 && j2 < WC)
            v = inb[i2*WC + j2];
        tile[idx] = v;
    }
    __syncthreads();

    for (int o = tid; o < TI*WC; o += 256) {
        int r = o / WC, j = o - r*WC;
        const float2* base = tile + r*PW + j;
        float acc = bs;
        #pragma unroll
        for (int kh = 0; kh < 7; ++kh) {
            #pragma unroll
            for (int kw = 0; kw < 7; ++kw) {
                float2 v = base[kh*PW + kw];
                float2 w = wsm[kh*7 + kw];
                acc = fmaf(v.x, w.x, acc);
                acc = fmaf(v.y, w.y, acc);
            }
        }
        float y = acc*sc + sh;
        float a = 1.f / (1.f + __expf(-y));
        int i = i0 + r;
        size_t oo = MODE ? ((size_t)b*WC + j)*HC + i
                         : ((size_t)b*HC + i)*WC + j;
        out[oo] = a;
    }
}

__global__ void conv_all_kernel(
    const float* __restrict__ c1w, const float* __restrict__ c1b,
    const float* __restrict__ b1g, const float* __restrict__ b1b,
    const float* __restrict__ b1m, const float* __restrict__ b1v,
    const float* __restrict__ c2w, const float* __restrict__ c2b,
    const float* __restrict__ b2g, const float* __restrict__ b2b,
    const float* __restrict__ b2m, const float* __restrict__ b2v,
    const float* __restrict__ c3w, const float* __restrict__ c3b,
    const float* __restrict__ b3g, const float* __restrict__ b3b,
    const float* __restrict__ b3m, const float* __restrict__ b3v)
{
    __shared__ float2 tile[14*262];
    __shared__ float2 wsm[49];

    int bx = blockIdx.x;
    int which, b, t0;
    const float *wc, *bc, *bg, *bb, *bm, *bv;
    if (bx < 224)        { which = 0; int r = bx;        b = r/7;  t0 = r%7;
                           wc=c1w; bc=c1b; bg=b1g; bb=b1b; bm=b1m; bv=b1v; }
    else if (bx < 1248)  { which = 1; int r = bx - 224;  b = r/32; t0 = r%32;
                           wc=c2w; bc=c2b; bg=b2g; bb=b2b; bm=b2m; bv=b2v; }
    else                 { which = 2; int r = bx - 1248; b = r/7;  t0 = r%7;
                           wc=c3w; bc=c3b; bg=b3g; bb=b3b; bm=b3m; bv=b3v; }

    if (threadIdx.x < 49) wsm[threadIdx.x] = ((const float2*)wc)[threadIdx.x];
    float sc = bg[0] * rsqrtf(bv[0] + 1e-3f);
    float sh = bb[0] - bm[0]*sc;
    float bs = bc[0];
    __syncthreads();

    if (which == 0)
        do_conv<HH, CC, 0>(tile, wsm, g_pool1, g_a1,  b, t0, sc, sh, bs);
    else if (which == 1)
        do_conv<CC, WW, 1>(tile, wsm, g_pool2, g_a2t, b, t0, sc, sh, bs);
    else
        do_conv<HH, WW, 0>(tile, wsm, g_pool3, g_a3,  b, t0, sc, sh, bs);
}

// ---------------- gap partials: sum_w x*(a1+a2+a3), per (b,h,c) ------------------
__global__ __launch_bounds__(256) void gap_kernel(const float* __restrict__ x) {
    int t = threadIdx.x;
    int sub = t >> 6, c4 = t & 63;
    int b = blockIdx.x / 14, hq = blockIdx.x % 14;
    int h = hq*4 + sub;
    int bh = b*HH + h;
    const float* xp  = x + (size_t)bh*(WW*CC) + c4*4;
    const float* a2p = g_a2t + (size_t)b*WW*CC + c4*4;
    const float* a3p = g_a3 + bh*WW;
    float4 ra1 = *((const float4*)(g_a1 + (size_t)bh*CC) + c4);
    float4 acc = make_float4(0.f,0.f,0.f,0.f);
    #pragma unroll 8
    for (int w = 0; w < WW; ++w) {
        float4 xv = *(const float4*)(xp + w*CC);
        float4 a2 = *(const float4*)(a2p + w*CC);
        float a3 = a3p[w];
        acc.x = fmaf(xv.x, ra1.x + a2.x + a3, acc.x);
        acc.y = fmaf(xv.y, ra1.y + a2.y + a3, acc.y);
        acc.z = fmaf(xv.z, ra1.z + a2.z + a3, acc.z);
        acc.w = fmaf(xv.w, ra1.w + a2.w + a3, acc.w);
    }
    *((float4*)(g_gpart + (size_t)bh*CC) + c4) = acc;
}

// ---------------- SE MLP: 256 -> 32 (relu) -> 256 (sigmoid), all warps active ----
__global__ __launch_bounds__(256) void se_kernel(
        const float* __restrict__ w1, const float* __restrict__ b1,
        const float* __restrict__ w2, const float* __restrict__ b2) {
    int b = blockIdx.x;
    int t = threadIdx.x;
    __shared__ float g[CC];
    __shared__ float hbuf[32];

    // gap finalize: thread t owns channel t (coalesced over h)
    float s = 0.f;
    #pragma unroll 8
    for (int h = 0; h < HH; ++h) s += g_gpart[((size_t)b*HH + h)*CC + t];
    g[t] = s * (1.f/(HH*WW));
    __syncthreads();

    // layer 1: 32 hidden units x 8-thread slices; 32 independent w1 loads/thread
    int d = t >> 3, grp = t & 7;
    float a = 0.f;
    #pragma unroll
    for (int k = 0; k < 32; ++k) {
        int c = grp + 8*k;
        a = fmaf(g[c], __ldg(w1 + c*32 + d), a);
    }
    a += __shfl_xor_sync(0xFFFFFFFFu, a, 1);
    a += __shfl_xor_sync(0xFFFFFFFFu, a, 2);
    a += __shfl_xor_sync(0xFFFFFFFFu, a, 4);
    if (grp == 0) hbuf[d] = fmaxf(a + __ldg(b1 + d), 0.f);
    __syncthreads();

    // layer 2: thread t owns output channel t; 32 coalesced w2 loads
    float acc = __ldg(b2 + t);
    #pragma unroll
    for (int dd = 0; dd < 32; ++dd)
        acc = fmaf(hbuf[dd], __ldg(w2 + dd*CC + t), acc);
    g_cw[b*CC + t] = 1.f / (1.f + __expf(-acc));
}

// ---------------- final: out = x * (a1+a2+a3) * cw -------------------------------
__global__ __launch_bounds__(256) void final_kernel(const float* __restrict__ x,
                                                    float* __restrict__ out) {
    int t = threadIdx.x;
    int sub = t >> 6, c4 = t & 63;
    int b = blockIdx.x / 14, hq = blockIdx.x % 14;
    int h = hq*4 + sub;
    int bh = b*HH + h;
    size_t base = (size_t)bh*(WW*CC) + c4*4;
    const float* a2p = g_a2t + (size_t)b*WW*CC + c4*4;
    const float* a3p = g_a3 + bh*WW;
    float4 ra1 = *((const float4*)(g_a1 + (size_t)bh*CC) + c4);
    float4 rcw = *((const float4*)(g_cw + (size_t)b*CC) + c4);
    #pragma unroll 8
    for (int w = 0; w < WW; ++w) {
        float4 xv = *(const float4*)(x + base + w*CC);
        float4 a2 = *(const float4*)(a2p + w*CC);
        float a3 = a3p[w];
        float4 o;
        o.x = xv.x * (ra1.x + a2.x + a3) * rcw.x;
        o.y = xv.y * (ra1.y + a2.y + a3) * rcw.y;
        o.z = xv.z * (ra1.z + a2.z + a3) * rcw.z;
        o.w = xv.w * (ra1.w + a2.w + a3) * rcw.w;
        *(float4*)(out + base + w*CC) = o;
    }
}

// ---------------- launch ----------------------------------------------------------
extern "C" void kernel_launch(void* const* d_in, const int* in_sizes, int n_in,
                              void* d_out, int out_size) {
    const float* x   = (const float*)d_in[0];
    const float* c1w = (const float*)d_in[1];
    const float* c1b = (const float*)d_in[2];
    const float* b1g = (const float*)d_in[3];
    const float* b1b = (const float*)d_in[4];
    const float* b1m = (const float*)d_in[5];
    const float* b1v = (const float*)d_in[6];
    const float* c2w = (const float*)d_in[7];
    const float* c2b = (const float*)d_in[8];
    const float* b2g = (const float*)d_in[9];
    const float* b2b = (const float*)d_in[10];
    const float* b2m = (const float*)d_in[11];
    const float* b2v = (const float*)d_in[12];
    const float* c3w = (const float*)d_in[13];
    const float* c3b = (const float*)d_in[14];
    const float* b3g = (const float*)d_in[15];
    const float* b3b = (const float*)d_in[16];
    const float* b3m = (const float*)d_in[17];
    const float* b3v = (const float*)d_in[18];
    const float* sw1 = (const float*)d_in[19];
    const float* sb1 = (const float*)d_in[20];
    const float* sw2 = (const float*)d_in[21];
    const float* sb2 = (const float*)d_in[22];
    float* out = (float*)d_out;

    pools_kernel<<<2*NB, 256>>>(x);
    conv_all_kernel<<<1472, 256>>>(
        c1w, c1b, b1g, b1b, b1m, b1v,
        c2w, c2b, b2g, b2b, b2m, b2v,
        c3w, c3b, b3g, b3b, b3m, b3v);
    gap_kernel<<<NB, 256>>>(x);
    se_kernel<<<BB, 256>>>(sw1, sb1, sw2, sb2);
    final_kernel<<<NB, 256>>>(x, out);
}

// round 7
// speedup vs baseline: 1.3347x; 1.0423x over previous
#include <cuda_runtime.h>
#include <math.h>
#include <float.h>

#define BB 32
#define HH 56
#define WW 56
#define CC 256
#define HW (HH*WW)
#define NB (BB*14)   // 448 blocks per streaming pass (4 rows x 64 c-quads each)

// ---------------- scratch (device globals) ---------------------------------------
__device__ __align__(16) float g_pool1[BB*HH*CC*2];   // [b][h][c][{max,mean}]
__device__ __align__(16) float g_pool2[BB*CC*WW*2];   // [b][c][w][{max,mean}]
__device__ __align__(16) float g_pool3[BB*HH*WW*2];   // [b][h][w][{max,mean}]
__device__ __align__(16) float g_a1 [BB*HH*CC];       // [b][h][c]
__device__ __align__(16) float g_a2t[BB*WW*CC];       // [b][w][c]
__device__ __align__(16) float g_a3 [BB*HH*WW];       // [b][h][w]
__device__ __align__(16) float g_gap[BB*CC];          // atomically-reduced gap sums
__device__ __align__(16) float g_cw[BB*CC];           // SE channel gate
__device__ unsigned int g_ticket[BB];                 // monotonic arrival tickets
__device__ unsigned int g_flag[BB];                   // monotonic per-batch done flag

__device__ __forceinline__ float4 f4max(float4 a, float4 b) {
    return make_float4(fmaxf(a.x,b.x), fmaxf(a.y,b.y), fmaxf(a.z,b.z), fmaxf(a.w,b.w));
}

// ---------------- all three pools, one kernel (also zeroes g_gap) -----------------
__global__ __launch_bounds__(256) void pools_kernel(const float* __restrict__ x) {
    int t = threadIdx.x;
    int sub = t >> 6;          // 0..3
    int c4  = t & 63;          // c-quad index

    if (blockIdx.x < 32) g_gap[blockIdx.x*CC + t] = 0.f;   // zero for gsf atomics

    if (blockIdx.x < NB) {
        int b = blockIdx.x / 14, hq = blockIdx.x % 14;
        int h = hq*4 + sub;
        int bh = b*HH + h;
        const float* xp = x + (size_t)bh*(WW*CC) + c4*4;

        int lane = t & 31;
        int half = c4 >> 5;
        __shared__ float2 s3[4][WW][2];

        float4 mx = make_float4(-FLT_MAX,-FLT_MAX,-FLT_MAX,-FLT_MAX);
        float4 sm = make_float4(0.f,0.f,0.f,0.f);
        #pragma unroll 8
        for (int w = 0; w < WW; ++w) {
            float4 v = *(const float4*)(xp + w*CC);
            mx = f4max(mx, v);
            sm.x += v.x; sm.y += v.y; sm.z += v.z; sm.w += v.w;
            float m = fmaxf(fmaxf(v.x,v.y), fmaxf(v.z,v.w));
            float s = v.x+v.y+v.z+v.w;
            #pragma unroll
            for (int off = 16; off; off >>= 1) {
                m = fmaxf(m, __shfl_xor_sync(0xFFFFFFFFu, m, off));
                s += __shfl_xor_sync(0xFFFFFFFFu, s, off);
            }
            if (lane == 0) s3[sub][w][half] = make_float2(m, s);
        }
        {
            const float invw = 1.f/WW;
            float4* o = (float4*)(g_pool1 + ((size_t)bh*CC + c4*4)*2);
            o[0] = make_float4(mx.x, sm.x*invw, mx.y, sm.y*invw);
            o[1] = make_float4(mx.z, sm.z*invw, mx.w, sm.w*invw);
        }
        __syncthreads();
        if (t < 224) {
            int hl = t / WW, w = t % WW;
            float2 p0 = s3[hl][w][0], p1 = s3[hl][w][1];
            int o = ((b*HH + hq*4 + hl)*WW + w)*2;
            g_pool3[o]   = fmaxf(p0.x, p1.x);
            g_pool3[o+1] = (p0.y + p1.y) * (1.f/CC);
        }
    } else {
        int blk = blockIdx.x - NB;
        int b = blk / 14, wq = blk % 14;
        int w = wq*4 + sub;
        const float* xp = x + ((size_t)b*HW + w)*CC + c4*4;
        float4 mx = make_float4(-FLT_MAX,-FLT_MAX,-FLT_MAX,-FLT_MAX);
        float4 sm = make_float4(0.f,0.f,0.f,0.f);
        #pragma unroll 8
        for (int h = 0; h < HH; ++h) {
            float4 v = *(const float4*)(xp + (size_t)h*WW*CC);
            mx = f4max(mx, v);
            sm.x += v.x; sm.y += v.y; sm.z += v.z; sm.w += v.w;
        }
        const float invh = 1.f/HH;
        float2* o = (float2*)g_pool2 + ((size_t)b*CC + c4*4)*WW + w;
        o[0]    = make_float2(mx.x, sm.x*invh);
        o[WW]   = make_float2(mx.y, sm.y*invh);
        o[2*WW] = make_float2(mx.z, sm.z*invh);
        o[3*WW] = make_float2(mx.w, sm.w*invh);
    }
}

// ---------------- 7x7 conv (2ch->1) + BN + sigmoid, smem-tiled, branchless -------
template<int HC, int WC, int MODE>
__device__ __forceinline__ void do_conv(
    float2* tile, float2* wsm,
    const float* __restrict__ in, float* __restrict__ out,
    int b, int t0, float sc, float sh, float bs)
{
    const int TI = 8;
    const int PW = WC + 6;
    int tid = threadIdx.x;
    int i0 = t0 * TI;

    const float2* inb = (const float2*)in + (size_t)b*HC*WC;
    for (int idx = tid; idx < (TI+6)*PW; idx += 256) {
        int r = idx / PW, col = idx - r*PW;
        int i2 = i0 + r - 3, j2 = col - 3;
        float2 v = make_float2(0.f, 0.f);
        if (i2 >= 0 && i2 < HC && j2 >= 0 && j2 < WC)
            v = inb[i2*WC + j2];
        tile[idx] = v;
    }
    __syncthreads();

    for (int o = tid; o < TI*WC; o += 256) {
        int r = o / WC, j = o - r*WC;
        const float2* base = tile + r*PW + j;
        float acc = bs;
        #pragma unroll
        for (int kh = 0; kh < 7; ++kh) {
            #pragma unroll
            for (int kw = 0; kw < 7; ++kw) {
                float2 v = base[kh*PW + kw];
                float2 w = wsm[kh*7 + kw];
                acc = fmaf(v.x, w.x, acc);
                acc = fmaf(v.y, w.y, acc);
            }
        }
        float y = acc*sc + sh;
        float a = 1.f / (1.f + __expf(-y));
        int i = i0 + r;
        size_t oo = MODE ? ((size_t)b*WC + j)*HC + i
                         : ((size_t)b*HC + i)*WC + j;
        out[oo] = a;
    }
}

__global__ void conv_all_kernel(
    const float* __restrict__ c1w, const float* __restrict__ c1b,
    const float* __restrict__ b1g, const float* __restrict__ b1b,
    const float* __restrict__ b1m, const float* __restrict__ b1v,
    const float* __restrict__ c2w, const float* __restrict__ c2b,
    const float* __restrict__ b2g, const float* __restrict__ b2b,
    const float* __restrict__ b2m, const float* __restrict__ b2v,
    const float* __restrict__ c3w, const float* __restrict__ c3b,
    const float* __restrict__ b3g, const float* __restrict__ b3b,
    const float* __restrict__ b3m, const float* __restrict__ b3v)
{
    __shared__ float2 tile[14*262];
    __shared__ float2 wsm[49];

    int bx = blockIdx.x;
    int which, b, t0;
    const float *wc, *bc, *bg, *bb, *bm, *bv;
    if (bx < 224)        { which = 0; int r = bx;        b = r/7;  t0 = r%7;
                           wc=c1w; bc=c1b; bg=b1g; bb=b1b; bm=b1m; bv=b1v; }
    else if (bx < 1248)  { which = 1; int r = bx - 224;  b = r/32; t0 = r%32;
                           wc=c2w; bc=c2b; bg=b2g; bb=b2b; bm=b2m; bv=b2v; }
    else                 { which = 2; int r = bx - 1248; b = r/7;  t0 = r%7;
                           wc=c3w; bc=c3b; bg=b3g; bb=b3b; bm=b3m; bv=b3v; }

    if (threadIdx.x < 49) wsm[threadIdx.x] = ((const float2*)wc)[threadIdx.x];
    float sc = bg[0] * rsqrtf(bv[0] + 1e-3f);
    float sh = bb[0] - bm[0]*sc;
    float bs = bc[0];
    __syncthreads();

    if (which == 0)
        do_conv<HH, CC, 0>(tile, wsm, g_pool1, g_a1,  b, t0, sc, sh, bs);
    else if (which == 1)
        do_conv<CC, WW, 1>(tile, wsm, g_pool2, g_a2t, b, t0, sc, sh, bs);
    else
        do_conv<HH, WW, 0>(tile, wsm, g_pool3, g_a3,  b, t0, sc, sh, bs);
}

// ---------------- fused gap + SE + final ------------------------------------------
// block = (b, hq). gap phase -> atomic reduce -> last block per b runs SE ->
// other blocks wait on flag -> all blocks run the final elementwise pass.
__global__ __launch_bounds__(256, 4) void gsf_kernel(
        const float* __restrict__ x, float* __restrict__ out,
        const float* __restrict__ w1, const float* __restrict__ b1,
        const float* __restrict__ w2, const float* __restrict__ b2) {
    int t = threadIdx.x;
    int sub = t >> 6, c4 = t & 63;
    int b = blockIdx.x / 14, hq = blockIdx.x % 14;
    int h = hq*4 + sub;
    int bh = b*HH + h;

    __shared__ unsigned int s_f0;
    __shared__ int s_last;
    if (t == 0) s_f0 = atomicAdd(&g_flag[b], 0u);   // snapshot BEFORE ticketing

    size_t base = (size_t)bh*(WW*CC) + c4*4;
    const float* a2p = g_a2t + (size_t)b*WW*CC + c4*4;
    const float* a3p = g_a3 + bh*WW;
    float4 ra1 = *((const float4*)(g_a1 + (size_t)bh*CC) + c4);

    // ---- gap phase ----
    float4 acc = make_float4(0.f,0.f,0.f,0.f);
    #pragma unroll 8
    for (int w = 0; w < WW; ++w) {
        float4 xv = *(const float4*)(x + base + w*CC);
        float4 a2 = *(const float4*)(a2p + w*CC);
        float a3 = a3p[w];
        acc.x = fmaf(xv.x, ra1.x + a2.x + a3, acc.x);
        acc.y = fmaf(xv.y, ra1.y + a2.y + a3, acc.y);
        acc.z = fmaf(xv.z, ra1.z + a2.z + a3, acc.z);
        acc.w = fmaf(xv.w, ra1.w + a2.w + a3, acc.w);
    }
    __shared__ float4 sa[4][64];
    sa[sub][c4] = acc;
    __syncthreads();
    if (t < 64) {
        float4 s = sa[0][t];
        #pragma unroll
        for (int g = 1; g < 4; ++g) {
            float4 q = sa[g][t];
            s.x += q.x; s.y += q.y; s.z += q.z; s.w += q.w;
        }
        float* gp = g_gap + b*CC + t*4;
        atomicAdd(gp+0, s.x);
        atomicAdd(gp+1, s.y);
        atomicAdd(gp+2, s.z);
        atomicAdd(gp+3, s.w);
    }
    __threadfence();                                 // release our partial sums
    if (t == 0) {
        unsigned int old = atomicAdd(&g_ticket[b], 1u);
        s_last = ((old % 14u) == 13u);
    }
    __syncthreads();

    if (s_last) {
        // ---- SE for batch b (all partials visible: peers fenced before ticket) ----
        __threadfence();                             // acquire
        __shared__ float g[CC];
        __shared__ float hbuf[32];
        g[t] = g_gap[b*CC + t] * (1.f/(HH*WW));
        __syncthreads();
        int d = t >> 3, grp = t & 7;
        float a = 0.f;
        #pragma unroll
        for (int k = 0; k < 32; ++k) {
            int c = grp + 8*k;
            a = fmaf(g[c], __ldg(w1 + c*32 + d), a);
        }
        a += __shfl_xor_sync(0xFFFFFFFFu, a, 1);
        a += __shfl_xor_sync(0xFFFFFFFFu, a, 2);
        a += __shfl_xor_sync(0xFFFFFFFFu, a, 4);
        if (grp == 0) hbuf[d] = fmaxf(a + __ldg(b1 + d), 0.f);
        __syncthreads();
        float av = __ldg(b2 + t);
        #pragma unroll
        for (int dd = 0; dd < 32; ++dd)
            av = fmaf(hbuf[dd], __ldg(w2 + dd*CC + t), av);
        g_cw[b*CC + t] = 1.f / (1.f + __expf(-av));
        __threadfence();                             // release cw
        __syncthreads();
        if (t == 0) atomicAdd(&g_flag[b], 1u);
    } else {
        if (t == 0) {
            while (atomicAdd(&g_flag[b], 0u) == s_f0) __nanosleep(200);
        }
        __syncthreads();
        __threadfence();                             // acquire cw
    }

    // ---- final phase: out = x * (a1+a2+a3) * cw ----
    float4 rcw = *((const float4*)(g_cw + (size_t)b*CC) + c4);
    #pragma unroll 8
    for (int w = 0; w < WW; ++w) {
        float4 xv = *(const float4*)(x + base + w*CC);
        float4 a2 = *(const float4*)(a2p + w*CC);
        float a3 = a3p[w];
        float4 o;
        o.x = xv.x * (ra1.x + a2.x + a3) * rcw.x;
        o.y = xv.y * (ra1.y + a2.y + a3) * rcw.y;
        o.z = xv.z * (ra1.z + a2.z + a3) * rcw.z;
        o.w = xv.w * (ra1.w + a2.w + a3) * rcw.w;
        *(float4*)(out + base + w*CC) = o;
    }
}

// ---------------- launch ----------------------------------------------------------
extern "C" void kernel_launch(void* const* d_in, const int* in_sizes, int n_in,
                              void* d_out, int out_size) {
    const float* x   = (const float*)d_in[0];
    const float* c1w = (const float*)d_in[1];
    const float* c1b = (const float*)d_in[2];
    const float* b1g = (const float*)d_in[3];
    const float* b1b = (const float*)d_in[4];
    const float* b1m = (const float*)d_in[5];
    const float* b1v = (const float*)d_in[6];
    const float* c2w = (const float*)d_in[7];
    const float* c2b = (const float*)d_in[8];
    const float* b2g = (const float*)d_in[9];
    const float* b2b = (const float*)d_in[10];
    const float* b2m = (const float*)d_in[11];
    const float* b2v = (const float*)d_in[12];
    const float* c3w = (const float*)d_in[13];
    const float* c3b = (const float*)d_in[14];
    const float* b3g = (const float*)d_in[15];
    const float* b3b = (const float*)d_in[16];
    const float* b3m = (const float*)d_in[17];
    const float* b3v = (const float*)d_in[18];
    const float* sw1 = (const float*)d_in[19];
    const float* sb1 = (const float*)d_in[20];
    const float* sw2 = (const float*)d_in[21];
    const float* sb2 = (const float*)d_in[22];
    float* out = (float*)d_out;

    pools_kernel<<<2*NB, 256>>>(x);
    conv_all_kernel<<<1472, 256>>>(
        c1w, c1b, b1g, b1b, b1m, b1v,
        c2w, c2b, b2g, b2b, b2m, b2v,
        c3w, c3b, b3g, b3b, b3m, b3v);
    gsf_kernel<<<NB, 256>>>(x, out, sw1, sb1, sw2, sb2);
}